// round 1
// baseline (speedup 1.0000x reference)
#include <cuda_runtime.h>
#include <math.h>

// Fixed problem shapes (from reference): x (4, 32, 8192, 64) fp32, pos arange(8192)
#define SEQ      8192
#define NPAIR    32          // d_k/2
#define NF4_ROW  16          // 64 floats per row / 4

// cos/sin table: per position, 16 float4 = {cos_k, sin_k, cos_{k+1}, sin_{k+1}}
// 8192 * 16 * 16B = 2 MiB static device scratch (no allocation — guard-safe).
__device__ float4 g_rope_tab[SEQ * NF4_ROW];

__global__ void build_table_kernel(const int* __restrict__ token_positions) {
    int tid = blockIdx.x * blockDim.x + threadIdx.x;   // 0 .. SEQ*NPAIR-1
    if (tid >= SEQ * NPAIR) return;
    int p = tid >> 5;          // position index
    int k = tid & (NPAIR - 1); // frequency index
    // inv_freq = 10000^(-2k/64); round to fp32 like the reference, then round the
    // angle product to fp32 like the reference, then take trig at double precision
    // (strictly more accurate than the reference's fp32 trig).
    float invf  = (float)pow(10000.0, -2.0 * (double)k / 64.0);
    float angf  = (float)token_positions[p] * invf;
    double ang  = (double)angf;
    float2* tab = (float2*)g_rope_tab;
    tab[p * NPAIR + k] = make_float2((float)cos(ang), (float)sin(ang));
}

__global__ void __launch_bounds__(256)
rope_kernel(const float* __restrict__ x, float* __restrict__ out, int n4) {
    int i = blockIdx.x * blockDim.x + threadIdx.x;
    if (i >= n4) return;
    int j = i & (NF4_ROW - 1);        // which float4 within the 64-elem row
    int p = (i >> 4) & (SEQ - 1);     // position (seq index)

    float4 v = ((const float4*)x)[i];           // {e0, o0, e1, o1}
    float4 t = __ldg(&g_rope_tab[p * NF4_ROW + j]); // {c0, s0, c1, s1}

    float4 o;
    o.x = t.x * v.x - t.y * v.y;   // cos*e - sin*o
    o.y = t.y * v.x + t.x * v.y;   // sin*e + cos*o
    o.z = t.z * v.z - t.w * v.w;
    o.w = t.w * v.z + t.z * v.w;
    ((float4*)out)[i] = o;
}

extern "C" void kernel_launch(void* const* d_in, const int* in_sizes, int n_in,
                              void* d_out, int out_size) {
    const float* x   = (const float*)d_in[0];
    const int*   pos = (const int*)d_in[1];
    float*       out = (float*)d_out;

    // 1) Build cos/sin table (262144 threads, off the critical path)
    {
        int n = SEQ * NPAIR;
        build_table_kernel<<<(n + 255) / 256, 256>>>(pos);
    }
    // 2) Main RoPE pass: one thread per float4
    {
        int n4 = out_size / 4;                     // 16,777,216
        rope_kernel<<<(n4 + 255) / 256, 256>>>(x, out, n4);
    }
}

// round 2
// speedup vs baseline: 1.7256x; 1.7256x over previous
#include <cuda_runtime.h>
#include <math.h>

// Fixed problem shapes (from reference): x (4, 32, 8192, 64) fp32, pos arange(8192)
#define SEQ      8192
#define NPAIR    32          // d_k/2
#define NF4_ROW  16          // 64 floats per row / 4
#define N4_TOTAL (4 * 32 * SEQ * NF4_ROW)   // 16,777,216 float4s

// cos/sin table: per position, 16 float4 = {cos_k, sin_k, cos_{k+1}, sin_{k+1}}
// 2 MiB static device scratch (no allocation — guard-safe).
__device__ float4 g_rope_tab[SEQ * NF4_ROW];

// Table build: fp32 trig only. The 32 inv_freq values are computed once per
// block by 32 threads in double (tiny FP64 footprint), broadcast via smem.
// Angle is rounded to fp32 exactly like the reference (float(pos) * float(invf)).
__global__ void __launch_bounds__(256)
build_table_kernel(const int* __restrict__ token_positions) {
    __shared__ float s_invf[NPAIR];
    if (threadIdx.x < NPAIR) {
        // 10000^(-2k/64), computed in double, rounded to fp32 (matches jnp fp32
        // value to <=1 ulp; downstream fp32 trig error dominates anyway).
        s_invf[threadIdx.x] = (float)exp2(-2.0 * (double)threadIdx.x / 64.0
                                          * 13.287712379549449 /* log2(10000) */);
    }
    __syncthreads();

    int tid = blockIdx.x * blockDim.x + threadIdx.x;   // 0 .. SEQ*NPAIR-1
    if (tid >= SEQ * NPAIR) return;
    int p = tid >> 5;          // position index
    int k = tid & (NPAIR - 1); // frequency index

    float ang = (float)token_positions[p] * s_invf[k];
    float s, c;
    sincosf(ang, &s, &c);      // accurate fp32 path (NOT __sincosf)
    ((float2*)g_rope_tab)[p * NPAIR + k] = make_float2(c, s);
}

// Main pass: ILP=2 — each thread handles two independent float4s (front-batched
// LDG.128 x2) to raise MLP and close the DRAM% gap.
__global__ void __launch_bounds__(256)
rope_kernel(const float* __restrict__ x, float* __restrict__ out) {
    int i0 = blockIdx.x * blockDim.x + threadIdx.x;     // 0 .. N4_TOTAL/2 - 1
    int i1 = i0 + (N4_TOTAL / 2);

    int j0 = i0 & (NF4_ROW - 1);
    int p0 = (i0 >> 4) & (SEQ - 1);
    int j1 = i1 & (NF4_ROW - 1);
    int p1 = (i1 >> 4) & (SEQ - 1);

    float4 v0 = ((const float4*)x)[i0];
    float4 v1 = ((const float4*)x)[i1];
    float4 t0 = __ldg(&g_rope_tab[p0 * NF4_ROW + j0]);
    float4 t1 = __ldg(&g_rope_tab[p1 * NF4_ROW + j1]);

    float4 o0, o1;
    o0.x = t0.x * v0.x - t0.y * v0.y;
    o0.y = t0.y * v0.x + t0.x * v0.y;
    o0.z = t0.z * v0.z - t0.w * v0.w;
    o0.w = t0.w * v0.z + t0.z * v0.w;
    o1.x = t1.x * v1.x - t1.y * v1.y;
    o1.y = t1.y * v1.x + t1.x * v1.y;
    o1.z = t1.z * v1.z - t1.w * v1.w;
    o1.w = t1.w * v1.z + t1.z * v1.w;

    ((float4*)out)[i0] = o0;
    ((float4*)out)[i1] = o1;
}

extern "C" void kernel_launch(void* const* d_in, const int* in_sizes, int n_in,
                              void* d_out, int out_size) {
    const float* x   = (const float*)d_in[0];
    const int*   pos = (const int*)d_in[1];
    float*       out = (float*)d_out;

    // 1) Build cos/sin table (fp32 trig; ~4 us)
    {
        int n = SEQ * NPAIR;
        build_table_kernel<<<(n + 255) / 256, 256>>>(pos);
    }
    // 2) Main RoPE pass: two float4s per thread
    {
        int nthreads = N4_TOTAL / 2;                // 8,388,608
        rope_kernel<<<nthreads / 256, 256>>>(x, out);
    }
}

// round 3
// speedup vs baseline: 1.7592x; 1.0195x over previous
#include <cuda_runtime.h>
#include <math.h>

// Fixed shapes: x (4, 32, 8192, 64) fp32, token_positions = arange(8192)
#define SEQ       8192
#define NF4_ROW   16                  // 64 floats / 4 per row
#define BH        128                 // 4*32 slices
#define CHUNK     16                  // bh-slices per thread
#define NCHUNK    (BH / CHUNK)        // 8
#define SLICE_F4  (SEQ * NF4_ROW)     // 131072 float4 per slice
#define LOG2_THETA 13.287712379549449 // log2(10000)

__global__ void __launch_bounds__(256)
rope_fused(const float4* __restrict__ x, float4* __restrict__ out,
           const int* __restrict__ pos) {
    // 32 inv_freq values, computed once per block (tiny FP64 footprint),
    // correctly-rounded fp32 — matches jnp's value (R2 evidence: rel_err 4.8e-8).
    __shared__ float s_invf[32];
    if (threadIdx.x < 32)
        s_invf[threadIdx.x] =
            (float)exp2(-(double)threadIdx.x * (LOG2_THETA / 32.0));
    __syncthreads();

    int tid   = blockIdx.x * 256 + threadIdx.x;   // 0 .. 1,048,575
    int j     = tid & (NF4_ROW - 1);              // float4 within row
    int p     = (tid >> 4) & (SEQ - 1);           // seq position
    int chunk = tid >> 17;                        // 0..7 (which 16 bh-slices)

    size_t base = (size_t)chunk * CHUNK * SLICE_F4 + (size_t)p * NF4_ROW + j;
    const float4* xp = x   + base;
    float4*       op = out + base;

    // Front-batch the first 4 loads BEFORE the trig so DRAM latency hides it.
    float4 va0 = __ldcs(&xp[0 * SLICE_F4]);
    float4 va1 = __ldcs(&xp[1 * SLICE_F4]);
    float4 va2 = __ldcs(&xp[2 * SLICE_F4]);
    float4 va3 = __ldcs(&xp[3 * SLICE_F4]);

    // Angles for pairs k = 2j, 2j+1 — fp32 rounding identical to reference.
    float posf = (float)__ldg(&pos[p]);
    float c0, s0, c1, s1;
    sincosf(posf * s_invf[2 * j],     &s0, &c0);
    sincosf(posf * s_invf[2 * j + 1], &s1, &c1);

    #pragma unroll
    for (int g = 0; g < CHUNK / 4; g++) {
        // Preload next group of 4 (keeps >=4 LDG in flight past the stores).
        float4 vb0, vb1, vb2, vb3;
        if (g < CHUNK / 4 - 1) {
            const float4* xn = xp + (g + 1) * 4 * SLICE_F4;
            vb0 = __ldcs(&xn[0 * SLICE_F4]);
            vb1 = __ldcs(&xn[1 * SLICE_F4]);
            vb2 = __ldcs(&xn[2 * SLICE_F4]);
            vb3 = __ldcs(&xn[3 * SLICE_F4]);
        }

        float4* on = op + g * 4 * SLICE_F4;
        float4 o;
        o.x = c0 * va0.x - s0 * va0.y;  o.y = s0 * va0.x + c0 * va0.y;
        o.z = c1 * va0.z - s1 * va0.w;  o.w = s1 * va0.z + c1 * va0.w;
        __stcs(&on[0 * SLICE_F4], o);
        o.x = c0 * va1.x - s0 * va1.y;  o.y = s0 * va1.x + c0 * va1.y;
        o.z = c1 * va1.z - s1 * va1.w;  o.w = s1 * va1.z + c1 * va1.w;
        __stcs(&on[1 * SLICE_F4], o);
        o.x = c0 * va2.x - s0 * va2.y;  o.y = s0 * va2.x + c0 * va2.y;
        o.z = c1 * va2.z - s1 * va2.w;  o.w = s1 * va2.z + c1 * va2.w;
        __stcs(&on[2 * SLICE_F4], o);
        o.x = c0 * va3.x - s0 * va3.y;  o.y = s0 * va3.x + c0 * va3.y;
        o.z = c1 * va3.z - s1 * va3.w;  o.w = s1 * va3.z + c1 * va3.w;
        __stcs(&on[3 * SLICE_F4], o);

        va0 = vb0; va1 = vb1; va2 = vb2; va3 = vb3;
    }
}

extern "C" void kernel_launch(void* const* d_in, const int* in_sizes, int n_in,
                              void* d_out, int out_size) {
    const float4* x   = (const float4*)d_in[0];
    const int*    pos = (const int*)d_in[1];
    float4*       out = (float4*)d_out;

    // One fused kernel: 8192*16 (p,j) coords * 8 bh-chunks = 1,048,576 threads
    int nthreads = SEQ * NF4_ROW * NCHUNK;
    rope_fused<<<nthreads / 256, 256>>>(x, out, pos);
}

// round 4
// speedup vs baseline: 1.7837x; 1.0139x over previous
#include <cuda_runtime.h>
#include <math.h>

// Fixed shapes: x (4, 32, 8192, 64) fp32, token_positions = arange(8192)
#define SEQ       8192
#define NF4_ROW   16                  // 64 floats / 4 per row
#define BH        128                 // 4*32 slices
#define CHUNK     4                   // bh-slices per thread (trig reuse factor)
#define NCHUNK    (BH / CHUNK)        // 32
#define SLICE_F4  (SEQ * NF4_ROW)     // 131072 float4 per slice
#define LOG2_THETA 13.287712379549449 // log2(10000)

__global__ void __launch_bounds__(256)
rope_fused(const float4* __restrict__ x, float4* __restrict__ out,
           const int* __restrict__ pos) {
    // 32 inv_freq values, correctly-rounded fp32 (double exp2 done by 32 lanes
    // per block only; matches jnp's fp32 value — R2/R3 evidence rel_err ~5e-8).
    __shared__ float s_invf[32];
    if (threadIdx.x < 32)
        s_invf[threadIdx.x] =
            (float)exp2(-(double)threadIdx.x * (LOG2_THETA / 32.0));
    __syncthreads();

    int tid   = blockIdx.x * 256 + threadIdx.x;   // 0 .. 4,194,303
    int j     = tid & (NF4_ROW - 1);              // float4 within row
    int p     = (tid >> 4) & (SEQ - 1);           // seq position
    int chunk = tid >> 17;                        // 0..31 (which 4 bh-slices)

    size_t base = (size_t)chunk * CHUNK * SLICE_F4 + (size_t)p * NF4_ROW + j;
    const float4* xp = x   + base;
    float4*       op = out + base;

    // Front-batch ALL 4 loads before the trig: DRAM latency hides sincosf.
    float4 v0 = __ldcs(&xp[0 * SLICE_F4]);
    float4 v1 = __ldcs(&xp[1 * SLICE_F4]);
    float4 v2 = __ldcs(&xp[2 * SLICE_F4]);
    float4 v3 = __ldcs(&xp[3 * SLICE_F4]);

    // Angles for pairs k = 2j, 2j+1 — fp32 rounding identical to reference.
    float posf = (float)__ldg(&pos[p]);
    float c0, s0, c1, s1;
    sincosf(posf * s_invf[2 * j],     &s0, &c0);
    sincosf(posf * s_invf[2 * j + 1], &s1, &c1);

    float4 o;
    o.x = c0 * v0.x - s0 * v0.y;  o.y = s0 * v0.x + c0 * v0.y;
    o.z = c1 * v0.z - s1 * v0.w;  o.w = s1 * v0.z + c1 * v0.w;
    __stcs(&op[0 * SLICE_F4], o);
    o.x = c0 * v1.x - s0 * v1.y;  o.y = s0 * v1.x + c0 * v1.y;
    o.z = c1 * v1.z - s1 * v1.w;  o.w = s1 * v1.z + c1 * v1.w;
    __stcs(&op[1 * SLICE_F4], o);
    o.x = c0 * v2.x - s0 * v2.y;  o.y = s0 * v2.x + c0 * v2.y;
    o.z = c1 * v2.z - s1 * v2.w;  o.w = s1 * v2.z + c1 * v2.w;
    __stcs(&op[2 * SLICE_F4], o);
    o.x = c0 * v3.x - s0 * v3.y;  o.y = s0 * v3.x + c0 * v3.y;
    o.z = c1 * v3.z - s1 * v3.w;  o.w = s1 * v3.z + c1 * v3.w;
    __stcs(&op[3 * SLICE_F4], o);
}

extern "C" void kernel_launch(void* const* d_in, const int* in_sizes, int n_in,
                              void* d_out, int out_size) {
    const float4* x   = (const float4*)d_in[0];
    const int*    pos = (const int*)d_in[1];
    float4*       out = (float4*)d_out;

    // 8192*16 (p,j) coords * 32 bh-chunks = 4,194,304 threads
    int nthreads = SEQ * NF4_ROW * NCHUNK;
    rope_fused<<<nthreads / 256, 256>>>(x, out, pos);
}